// round 3
// baseline (speedup 1.0000x reference)
#include <cuda_runtime.h>
#include <cstdint>
#include <cstddef>

#define NN_MAX 100000
#define NE_MAX 1600000
#define DIN 256
#define DH 128
#define SB 512

typedef unsigned long long ull;

// ---------------------------------------------------------------- scratch
__device__ float g_xf[NN_MAX * DH];    // x @ W_f^T   (51.2 MB)
__device__ float g_xb[NN_MAX * DH];    // x @ W_b^T   (51.2 MB)
__device__ int   g_cnt_c[NN_MAX];      // in-degree  (edges only)
__device__ int   g_cnt_r[NN_MAX];      // out-degree (edges only)
__device__ float g_isr_in[NN_MAX];
__device__ float g_isr_out[NN_MAX];
__device__ int   g_off_c[NN_MAX];
__device__ int   g_off_r[NN_MAX];
__device__ int   g_cur_c[NN_MAX];
__device__ int   g_cur_r[NN_MAX];
__device__ int   g_bsum_c[SB];
__device__ int   g_bsum_r[SB];
__device__ ull   g_ef[NE_MAX];         // edges sorted by col: (row, w)
__device__ ull   g_eb[NE_MAX];         // edges sorted by row: (col, w)
__device__ unsigned g_or;              // dtype-detect OR accumulator
__device__ int      g_is64;            // 1 if edge_index is int64

__device__ __forceinline__ ull pack2(float lo, float hi) {
    ull r; asm("mov.b64 %0, {%1, %2};" : "=l"(r) : "f"(lo), "f"(hi)); return r;
}
__device__ __forceinline__ void unpack2(ull v, float& lo, float& hi) {
    asm("mov.b64 {%0, %1}, %2;" : "=f"(lo), "=f"(hi) : "l"(v));
}
__device__ __forceinline__ void fma2(ull& d, ull a, ull b, ull c) {
    asm("fma.rn.f32x2 %0, %1, %2, %3;" : "=l"(d) : "l"(a), "l"(b), "l"(c));
}

// Read edge_index element `idx` (element index, works for int32 or int64 storage)
__device__ __forceinline__ int edge_val(const void* ei, size_t idx) {
    if (g_is64) return (int)((const long long*)ei)[idx];
    return ((const int*)ei)[idx];
}

// ---------------------------------------------------------------- dtype detect
__global__ void zero_small_kernel(int M) {
    int n = blockIdx.x * blockDim.x + threadIdx.x;
    if (n == 0) g_or = 0u;
    if (n >= M) return;
    g_cnt_c[n] = 0;
    g_cnt_r[n] = 0;
}

// OR all odd 32-bit words in the first `nwords` words. If edge_index is int64
// (little-endian, values < 2^31) these are all-zero high halves; if int32 they
// are random edge ids -> OR != 0 with overwhelming probability.
__global__ void detect_kernel(const unsigned* __restrict__ w, int nwords) {
    unsigned acc = 0;
    int stride = gridDim.x * blockDim.x;
    for (int i = blockIdx.x * blockDim.x + threadIdx.x; 2 * i + 1 < nwords; i += stride)
        acc |= w[2 * i + 1];
    #pragma unroll
    for (int o = 16; o > 0; o >>= 1)
        acc |= __shfl_xor_sync(0xffffffffu, acc, o);
    if ((threadIdx.x & 31) == 0 && acc)
        atomicOr(&g_or, acc);
}

__global__ void set_flag_kernel() {
    g_is64 = (g_or == 0u) ? 1 : 0;
}

// ---------------------------------------------------------------- degrees
__global__ void count_deg_kernel(const void* __restrict__ ei, int E) {
    int e = blockIdx.x * blockDim.x + threadIdx.x;
    if (e >= E) return;
    int c = edge_val(ei, e);
    int r = edge_val(ei, (size_t)E + e);
    atomicAdd(&g_cnt_c[c], 1);
    atomicAdd(&g_cnt_r[r], 1);
}

__global__ void isr_kernel(int M) {
    int n = blockIdx.x * blockDim.x + threadIdx.x;
    if (n >= M) return;
    g_isr_in[n]  = rsqrtf((float)(g_cnt_c[n] + 1));   // +1 self loop
    g_isr_out[n] = rsqrtf((float)(g_cnt_r[n] + 1));
}

// ---------------------------------------------------------------- scan (2-level)
// sel: 0 -> (cnt_c, bsum_c, off_c, cur_c), 1 -> (cnt_r, ...)
__global__ void scan_block_sums(int sel, int M) {
    const int* cnt = sel ? g_cnt_r : g_cnt_c;
    int* bsum = sel ? g_bsum_r : g_bsum_c;
    __shared__ int s[SB];
    int t = threadIdx.x;
    int i = blockIdx.x * SB + t;
    s[t] = (i < M) ? cnt[i] : 0;
    __syncthreads();
    for (int d = SB >> 1; d > 0; d >>= 1) {
        if (t < d) s[t] += s[t + d];
        __syncthreads();
    }
    if (t == 0) bsum[blockIdx.x] = s[0];
}

__global__ void scan_bsum(int sel, int nb) {
    int* bsum = sel ? g_bsum_r : g_bsum_c;
    __shared__ int s[SB];
    int t = threadIdx.x;
    int v = (t < nb) ? bsum[t] : 0;
    s[t] = v;
    __syncthreads();
    for (int d = 1; d < SB; d <<= 1) {
        int tmp = (t >= d) ? s[t - d] : 0;
        __syncthreads();
        s[t] += tmp;
        __syncthreads();
    }
    if (t < nb) bsum[t] = s[t] - v;   // exclusive
}

__global__ void scan_final(int sel, int M) {
    const int* cnt = sel ? g_cnt_r : g_cnt_c;
    const int* bsum = sel ? g_bsum_r : g_bsum_c;
    int* off = sel ? g_off_r : g_off_c;
    int* cur = sel ? g_cur_r : g_cur_c;
    __shared__ int s[SB];
    int t = threadIdx.x;
    int i = blockIdx.x * SB + t;
    int v = (i < M) ? cnt[i] : 0;
    s[t] = v;
    __syncthreads();
    for (int d = 1; d < SB; d <<= 1) {
        int tmp = (t >= d) ? s[t - d] : 0;
        __syncthreads();
        s[t] += tmp;
        __syncthreads();
    }
    if (i < M) {
        int ex = s[t] - v + bsum[blockIdx.x];
        off[i] = ex;
        cur[i] = ex;
    }
}

// ---------------------------------------------------------------- fill (counting-sort permute)
__global__ void fill_kernel(const void* __restrict__ ei, int E) {
    int e = blockIdx.x * blockDim.x + threadIdx.x;
    if (e >= E) return;
    int c = edge_val(ei, e);
    int r = edge_val(ei, (size_t)E + e);
    float w = g_isr_out[r] * g_isr_in[c];
    unsigned wb = __float_as_uint(w);
    int pc = atomicAdd(&g_cur_c[c], 1);
    g_ef[pc] = (ull)(unsigned)r | ((ull)wb << 32);
    int pr = atomicAdd(&g_cur_r[r], 1);
    g_eb[pr] = (ull)(unsigned)c | ((ull)wb << 32);
}

// ---------------------------------------------------------------- fused GEMM
// g_xf[n] = x[n,:] @ W_f^T ; g_xb[n] = x[n,:] @ W_b^T
#define BM 64
#define BK 16
#define AS_STRIDE 68
#define BS_STRIDE 260

__global__ __launch_bounds__(128, 2)
void gemm_kernel(const float* __restrict__ x,
                 const float* __restrict__ Wf,
                 const float* __restrict__ Wb,
                 int M)
{
    __shared__ float As[BK * AS_STRIDE];
    __shared__ float Bs[BK * BS_STRIDE];

    const int t  = threadIdx.x;
    const int tx = t & 15;
    const int ty = t >> 4;
    const int m0 = blockIdx.x * BM;

    ull acc[8][8];
    #pragma unroll
    for (int m = 0; m < 8; ++m)
        #pragma unroll
        for (int j = 0; j < 8; ++j) acc[m][j] = 0ull;

    float4 stA[2];
    float4 stB[8];

    auto doLoad = [&](int k0) {
        #pragma unroll
        for (int r = 0; r < 2; ++r) {
            int idx = t + 128 * r;
            int m = idx >> 2, kq = idx & 3;
            int gm = m0 + m;
            if (gm < M)
                stA[r] = *(const float4*)(x + (size_t)gm * DIN + k0 + kq * 4);
            else
                stA[r] = make_float4(0.f, 0.f, 0.f, 0.f);
        }
        #pragma unroll
        for (int r = 0; r < 8; ++r) {
            int idx = t + 128 * r;
            int n = idx >> 2, kq = idx & 3;
            const float* src = (n < DH) ? (Wf + (size_t)n * DIN)
                                        : (Wb + (size_t)(n - DH) * DIN);
            stB[r] = *(const float4*)(src + k0 + kq * 4);
        }
    };

    auto doStore = [&]() {
        #pragma unroll
        for (int r = 0; r < 2; ++r) {
            int idx = t + 128 * r;
            int m = idx >> 2, kq = idx & 3;
            float* d = As + (kq * 4) * AS_STRIDE + m;
            d[0 * AS_STRIDE] = stA[r].x;
            d[1 * AS_STRIDE] = stA[r].y;
            d[2 * AS_STRIDE] = stA[r].z;
            d[3 * AS_STRIDE] = stA[r].w;
        }
        #pragma unroll
        for (int r = 0; r < 8; ++r) {
            int idx = t + 128 * r;
            int n = idx >> 2, kq = idx & 3;
            float* d = Bs + (kq * 4) * BS_STRIDE + n;
            d[0 * BS_STRIDE] = stB[r].x;
            d[1 * BS_STRIDE] = stB[r].y;
            d[2 * BS_STRIDE] = stB[r].z;
            d[3 * BS_STRIDE] = stB[r].w;
        }
    };

    doLoad(0);

    #pragma unroll 1
    for (int it = 0; it < DIN / BK; ++it) {
        __syncthreads();
        doStore();
        __syncthreads();
        if (it + 1 < DIN / BK) doLoad((it + 1) * BK);

        #pragma unroll
        for (int k = 0; k < BK; ++k) {
            const float* ar = As + k * AS_STRIDE + ty * 8;
            float4 a0 = *(const float4*)ar;
            float4 a1 = *(const float4*)(ar + 4);
            const float* br = Bs + k * BS_STRIDE + tx * 4;
            float4 b0 = *(const float4*)br;
            float4 b1 = *(const float4*)(br + 64);
            float4 b2 = *(const float4*)(br + 128);
            float4 b3 = *(const float4*)(br + 192);

            ull bb[8];
            bb[0] = pack2(b0.x, b0.y); bb[1] = pack2(b0.z, b0.w);
            bb[2] = pack2(b1.x, b1.y); bb[3] = pack2(b1.z, b1.w);
            bb[4] = pack2(b2.x, b2.y); bb[5] = pack2(b2.z, b2.w);
            bb[6] = pack2(b3.x, b3.y); bb[7] = pack2(b3.z, b3.w);

            float am[8] = {a0.x, a0.y, a0.z, a0.w, a1.x, a1.y, a1.z, a1.w};
            #pragma unroll
            for (int m = 0; m < 8; ++m) {
                ull a2 = pack2(am[m], am[m]);
                #pragma unroll
                for (int j = 0; j < 8; ++j) fma2(acc[m][j], a2, bb[j], acc[m][j]);
            }
        }
    }

    #pragma unroll
    for (int m = 0; m < 8; ++m) {
        int node = m0 + ty * 8 + m;
        if (node >= M) continue;
        #pragma unroll
        for (int g = 0; g < 4; ++g) {
            float4 o;
            unpack2(acc[m][g * 2 + 0], o.x, o.y);
            unpack2(acc[m][g * 2 + 1], o.z, o.w);
            int n = tx * 4 + g * 64;
            if (n < DH) *(float4*)(g_xf + (size_t)node * DH + n) = o;
            else        *(float4*)(g_xb + (size_t)node * DH + (n - DH)) = o;
        }
    }
}

// ---------------------------------------------------------------- gather (CSR SpMM, no atomics)
// One warp per destination node; lane handles 4 contiguous floats (float4).
// sel=0: forward  (elist=g_ef, off_c/cnt_c, feat=g_xf, cols [0,128))
// sel=1: backward (elist=g_eb, off_r/cnt_r, feat=g_xb, cols [128,256))
__global__ __launch_bounds__(256)
void gather_kernel(int sel, const float* __restrict__ bias,
                   float* __restrict__ y, int M)
{
    int lane = threadIdx.x & 31;
    int n = (blockIdx.x * blockDim.x + threadIdx.x) >> 5;
    if (n >= M) return;

    const ull* elist = sel ? g_eb : g_ef;
    const int* off   = sel ? g_off_r : g_off_c;
    const int* cnt   = sel ? g_cnt_r : g_cnt_c;
    const float* feat = sel ? g_xb : g_xf;
    int ycol0 = sel ? 32 : 0;

    int beg = off[n];
    int deg = cnt[n];

    float4 acc = ((const float4*)(bias + sel * DH))[lane];
    float ws = g_isr_in[n] * g_isr_out[n];
    float4 sv = ((const float4*)feat)[(size_t)n * 32 + lane];
    acc.x += sv.x * ws; acc.y += sv.y * ws;
    acc.z += sv.z * ws; acc.w += sv.w * ws;

    for (int base = 0; base < deg; base += 32) {
        int e = base + lane;
        ull pk = (e < deg) ? elist[beg + e] : 0ull;
        int m = min(32, deg - base);
        for (int j = 0; j < m; ++j) {
            ull p = __shfl_sync(0xffffffffu, pk, j);
            int src = (int)(unsigned)(p & 0xffffffffu);
            float w = __uint_as_float((unsigned)(p >> 32));
            float4 v = ((const float4*)feat)[(size_t)src * 32 + lane];
            acc.x += v.x * w; acc.y += v.y * w;
            acc.z += v.z * w; acc.w += v.w * w;
        }
    }

    ((float4*)y)[(size_t)n * 64 + ycol0 + lane] = acc;
}

// ---------------------------------------------------------------- launch
extern "C" void kernel_launch(void* const* d_in, const int* in_sizes, int n_in,
                              void* d_out, int out_size)
{
    const float* x    = (const float*)d_in[0];
    const void*  ei   = d_in[1];
    const float* Wf   = (const float*)d_in[2];
    const float* Wb   = (const float*)d_in[3];
    const float* bias = (const float*)d_in[4];
    float*       y    = (float*)d_out;

    int M  = in_sizes[0] / DIN;      // 100000
    int E2 = in_sizes[1];            // 2*E elements (any int dtype)
    int E  = E2 / 2;                 // 1600000
    int nb = (M + SB - 1) / SB;      // 196 (<= SB)

    // dtype detection (int32 vs int64 edge_index)
    zero_small_kernel<<<(M + 255) / 256, 256>>>(M);
    detect_kernel<<<296, 256>>>((const unsigned*)ei, E2);
    set_flag_kernel<<<1, 1>>>();

    count_deg_kernel<<<(E + 255) / 256, 256>>>(ei, E);
    isr_kernel<<<(M + 255) / 256, 256>>>(M);

    scan_block_sums<<<nb, SB>>>(0, M);
    scan_block_sums<<<nb, SB>>>(1, M);
    scan_bsum<<<1, SB>>>(0, nb);
    scan_bsum<<<1, SB>>>(1, nb);
    scan_final<<<nb, SB>>>(0, M);
    scan_final<<<nb, SB>>>(1, M);

    fill_kernel<<<(E + 255) / 256, 256>>>(ei, E);

    gemm_kernel<<<(M + BM - 1) / BM, 128>>>(x, Wf, Wb, M);

    int gblocks = (M * 32 + 255) / 256;
    gather_kernel<<<gblocks, 256>>>(0, bias, y, M);
    gather_kernel<<<gblocks, 256>>>(1, bias, y, M);
}

// round 4
// speedup vs baseline: 1.1552x; 1.1552x over previous
#include <cuda_runtime.h>
#include <cuda_fp16.h>
#include <cstdint>
#include <cstddef>

#define NN_MAX 100000
#define NE_MAX 1600000
#define DIN 256
#define DH 128
#define SB 512

typedef unsigned long long ull;

// ---------------------------------------------------------------- scratch
__device__ __half g_xf[NN_MAX * DH];   // x @ W_f^T  (fp16, 25.6 MB)
__device__ __half g_xb[NN_MAX * DH];   // x @ W_b^T  (fp16, 25.6 MB)
__device__ int   g_cnt_c[NN_MAX];
__device__ int   g_cnt_r[NN_MAX];
__device__ float g_isr_in[NN_MAX];
__device__ float g_isr_out[NN_MAX];
__device__ int   g_off_c[NN_MAX];
__device__ int   g_off_r[NN_MAX];
__device__ int   g_cur_c[NN_MAX];
__device__ int   g_cur_r[NN_MAX];
__device__ int   g_bsum_c[SB];
__device__ int   g_bsum_r[SB];
__device__ ull   g_ef[NE_MAX];         // edges sorted by col: (row, w)
__device__ ull   g_eb[NE_MAX];         // edges sorted by row: (col, w)
__device__ unsigned g_or;
__device__ int      g_is64;

__device__ __forceinline__ ull pack2(float lo, float hi) {
    ull r; asm("mov.b64 %0, {%1, %2};" : "=l"(r) : "f"(lo), "f"(hi)); return r;
}
__device__ __forceinline__ void unpack2(ull v, float& lo, float& hi) {
    asm("mov.b64 {%0, %1}, %2;" : "=f"(lo), "=f"(hi) : "l"(v));
}
__device__ __forceinline__ void fma2(ull& d, ull a, ull b, ull c) {
    asm("fma.rn.f32x2 %0, %1, %2, %3;" : "=l"(d) : "l"(a), "l"(b), "l"(c));
}

__device__ __forceinline__ int edge_val(const void* ei, size_t idx) {
    if (g_is64) return (int)((const long long*)ei)[idx];
    return ((const int*)ei)[idx];
}

// ---------------------------------------------------------------- dtype detect + zero
__global__ void zero_small_kernel(int M) {
    int n = blockIdx.x * blockDim.x + threadIdx.x;
    if (n == 0) g_or = 0u;
    if (n >= M) return;
    g_cnt_c[n] = 0;
    g_cnt_r[n] = 0;
}

__global__ void detect_kernel(const unsigned* __restrict__ w, int nwords) {
    unsigned acc = 0;
    int stride = gridDim.x * blockDim.x;
    for (int i = blockIdx.x * blockDim.x + threadIdx.x; 2 * i + 1 < nwords; i += stride)
        acc |= w[2 * i + 1];
    #pragma unroll
    for (int o = 16; o > 0; o >>= 1)
        acc |= __shfl_xor_sync(0xffffffffu, acc, o);
    if ((threadIdx.x & 31) == 0 && acc)
        atomicOr(&g_or, acc);
}

__global__ void set_flag_kernel() {
    g_is64 = (g_or == 0u) ? 1 : 0;
}

// ---------------------------------------------------------------- degrees
__global__ void count_deg_kernel(const void* __restrict__ ei, int E) {
    int e = blockIdx.x * blockDim.x + threadIdx.x;
    if (e >= E) return;
    int c = edge_val(ei, e);
    int r = edge_val(ei, (size_t)E + e);
    atomicAdd(&g_cnt_c[c], 1);
    atomicAdd(&g_cnt_r[r], 1);
}

__global__ void isr_kernel(int M) {
    int n = blockIdx.x * blockDim.x + threadIdx.x;
    if (n >= M) return;
    g_isr_in[n]  = rsqrtf((float)(g_cnt_c[n] + 1));
    g_isr_out[n] = rsqrtf((float)(g_cnt_r[n] + 1));
}

// ---------------------------------------------------------------- scan (2-level)
__global__ void scan_block_sums(int sel, int M) {
    const int* cnt = sel ? g_cnt_r : g_cnt_c;
    int* bsum = sel ? g_bsum_r : g_bsum_c;
    __shared__ int s[SB];
    int t = threadIdx.x;
    int i = blockIdx.x * SB + t;
    s[t] = (i < M) ? cnt[i] : 0;
    __syncthreads();
    for (int d = SB >> 1; d > 0; d >>= 1) {
        if (t < d) s[t] += s[t + d];
        __syncthreads();
    }
    if (t == 0) bsum[blockIdx.x] = s[0];
}

__global__ void scan_bsum(int sel, int nb) {
    int* bsum = sel ? g_bsum_r : g_bsum_c;
    __shared__ int s[SB];
    int t = threadIdx.x;
    int v = (t < nb) ? bsum[t] : 0;
    s[t] = v;
    __syncthreads();
    for (int d = 1; d < SB; d <<= 1) {
        int tmp = (t >= d) ? s[t - d] : 0;
        __syncthreads();
        s[t] += tmp;
        __syncthreads();
    }
    if (t < nb) bsum[t] = s[t] - v;
}

__global__ void scan_final(int sel, int M) {
    const int* cnt = sel ? g_cnt_r : g_cnt_c;
    const int* bsum = sel ? g_bsum_r : g_bsum_c;
    int* off = sel ? g_off_r : g_off_c;
    int* cur = sel ? g_cur_r : g_cur_c;
    __shared__ int s[SB];
    int t = threadIdx.x;
    int i = blockIdx.x * SB + t;
    int v = (i < M) ? cnt[i] : 0;
    s[t] = v;
    __syncthreads();
    for (int d = 1; d < SB; d <<= 1) {
        int tmp = (t >= d) ? s[t - d] : 0;
        __syncthreads();
        s[t] += tmp;
        __syncthreads();
    }
    if (i < M) {
        int ex = s[t] - v + bsum[blockIdx.x];
        off[i] = ex;
        cur[i] = ex;
    }
}

// ---------------------------------------------------------------- fill
__global__ void fill_kernel(const void* __restrict__ ei, int E) {
    int e = blockIdx.x * blockDim.x + threadIdx.x;
    if (e >= E) return;
    int c = edge_val(ei, e);
    int r = edge_val(ei, (size_t)E + e);
    float w = g_isr_out[r] * g_isr_in[c];
    unsigned wb = __float_as_uint(w);
    int pc = atomicAdd(&g_cur_c[c], 1);
    g_ef[pc] = (ull)(unsigned)r | ((ull)wb << 32);
    int pr = atomicAdd(&g_cur_r[r], 1);
    g_eb[pr] = (ull)(unsigned)c | ((ull)wb << 32);
}

// ---------------------------------------------------------------- fused GEMM (fp32 math, fp16 out)
#define BM 64
#define BK 16
#define AS_STRIDE 68
#define BS_STRIDE 260

__global__ __launch_bounds__(128, 2)
void gemm_kernel(const float* __restrict__ x,
                 const float* __restrict__ Wf,
                 const float* __restrict__ Wb,
                 int M)
{
    __shared__ __align__(16) float As[BK * AS_STRIDE];
    __shared__ __align__(16) float Bs[BK * BS_STRIDE];

    const int t  = threadIdx.x;
    const int tx = t & 15;
    const int ty = t >> 4;
    const int m0 = blockIdx.x * BM;

    ull acc[8][8];
    #pragma unroll
    for (int m = 0; m < 8; ++m)
        #pragma unroll
        for (int j = 0; j < 8; ++j) acc[m][j] = 0ull;

    float4 stA[2];
    float4 stB[8];

    auto doLoad = [&](int k0) {
        #pragma unroll
        for (int r = 0; r < 2; ++r) {
            int idx = t + 128 * r;
            int m = idx >> 2, kq = idx & 3;
            int gm = m0 + m;
            if (gm < M)
                stA[r] = *(const float4*)(x + (size_t)gm * DIN + k0 + kq * 4);
            else
                stA[r] = make_float4(0.f, 0.f, 0.f, 0.f);
        }
        #pragma unroll
        for (int r = 0; r < 8; ++r) {
            int idx = t + 128 * r;
            int n = idx >> 2, kq = idx & 3;
            const float* src = (n < DH) ? (Wf + (size_t)n * DIN)
                                        : (Wb + (size_t)(n - DH) * DIN);
            stB[r] = *(const float4*)(src + k0 + kq * 4);
        }
    };

    auto doStore = [&]() {
        #pragma unroll
        for (int r = 0; r < 2; ++r) {
            int idx = t + 128 * r;
            int m = idx >> 2, kq = idx & 3;
            float* d = As + (kq * 4) * AS_STRIDE + m;
            d[0 * AS_STRIDE] = stA[r].x;
            d[1 * AS_STRIDE] = stA[r].y;
            d[2 * AS_STRIDE] = stA[r].z;
            d[3 * AS_STRIDE] = stA[r].w;
        }
        #pragma unroll
        for (int r = 0; r < 8; ++r) {
            int idx = t + 128 * r;
            int n = idx >> 2, kq = idx & 3;
            float* d = Bs + (kq * 4) * BS_STRIDE + n;
            d[0 * BS_STRIDE] = stB[r].x;
            d[1 * BS_STRIDE] = stB[r].y;
            d[2 * BS_STRIDE] = stB[r].z;
            d[3 * BS_STRIDE] = stB[r].w;
        }
    };

    doLoad(0);

    #pragma unroll 1
    for (int it = 0; it < DIN / BK; ++it) {
        __syncthreads();
        doStore();
        __syncthreads();
        if (it + 1 < DIN / BK) doLoad((it + 1) * BK);

        #pragma unroll
        for (int k = 0; k < BK; ++k) {
            const float* ar = As + k * AS_STRIDE + ty * 8;
            float4 a0 = *(const float4*)ar;
            float4 a1 = *(const float4*)(ar + 4);
            const float* br = Bs + k * BS_STRIDE + tx * 4;
            // direct 64-bit-pair loads: registers are ready-packed f32x2 operands
            ulonglong2 B0 = *(const ulonglong2*)br;
            ulonglong2 B1 = *(const ulonglong2*)(br + 64);
            ulonglong2 B2 = *(const ulonglong2*)(br + 128);
            ulonglong2 B3 = *(const ulonglong2*)(br + 192);
            ull bb[8] = {B0.x, B0.y, B1.x, B1.y, B2.x, B2.y, B3.x, B3.y};

            float am[8] = {a0.x, a0.y, a0.z, a0.w, a1.x, a1.y, a1.z, a1.w};
            #pragma unroll
            for (int m = 0; m < 8; ++m) {
                ull a2 = pack2(am[m], am[m]);
                #pragma unroll
                for (int j = 0; j < 8; ++j) fma2(acc[m][j], a2, bb[j], acc[m][j]);
            }
        }
    }

    #pragma unroll
    for (int m = 0; m < 8; ++m) {
        int node = m0 + ty * 8 + m;
        if (node >= M) continue;
        #pragma unroll
        for (int g = 0; g < 4; ++g) {
            float4 o;
            unpack2(acc[m][g * 2 + 0], o.x, o.y);
            unpack2(acc[m][g * 2 + 1], o.z, o.w);
            __half2 h0 = __floats2half2_rn(o.x, o.y);
            __half2 h1 = __floats2half2_rn(o.z, o.w);
            uint2 st;
            st.x = *(unsigned*)&h0;
            st.y = *(unsigned*)&h1;
            int n = tx * 4 + g * 64;
            if (n < DH) *(uint2*)(g_xf + (size_t)node * DH + n) = st;
            else        *(uint2*)(g_xb + (size_t)node * DH + (n - DH)) = st;
        }
    }
}

// ---------------------------------------------------------------- gather (CSR, fp16 features)
__global__ __launch_bounds__(256)
void gather_kernel(int sel, const float* __restrict__ bias,
                   float* __restrict__ y, int M)
{
    int lane = threadIdx.x & 31;
    int n = (blockIdx.x * blockDim.x + threadIdx.x) >> 5;
    if (n >= M) return;

    const ull* elist    = sel ? g_eb : g_ef;
    const int* off      = sel ? g_off_r : g_off_c;
    const int* cnt      = sel ? g_cnt_r : g_cnt_c;
    const __half* feat  = sel ? g_xb : g_xf;
    int ycol0 = sel ? 32 : 0;

    int beg = off[n];
    int deg = cnt[n];

    float4 acc = ((const float4*)(bias + sel * DH))[lane];
    {
        float ws = g_isr_in[n] * g_isr_out[n];
        uint2 rv = *(const uint2*)(feat + (size_t)n * DH + lane * 4);
        float2 f0 = __half22float2(*(__half2*)&rv.x);
        float2 f1 = __half22float2(*(__half2*)&rv.y);
        acc.x += f0.x * ws; acc.y += f0.y * ws;
        acc.z += f1.x * ws; acc.w += f1.y * ws;
    }

    for (int base = 0; base < deg; base += 32) {
        int e = base + lane;
        ull pk = (e < deg) ? elist[beg + e] : 0ull;
        int m = min(32, deg - base);
        for (int j = 0; j < m; ++j) {
            ull p = __shfl_sync(0xffffffffu, pk, j);
            int src = (int)(unsigned)(p & 0xffffffffu);
            float w = __uint_as_float((unsigned)(p >> 32));
            uint2 rv = *(const uint2*)(feat + (size_t)src * DH + lane * 4);
            float2 f0 = __half22float2(*(__half2*)&rv.x);
            float2 f1 = __half22float2(*(__half2*)&rv.y);
            acc.x += f0.x * w; acc.y += f0.y * w;
            acc.z += f1.x * w; acc.w += f1.y * w;
        }
    }

    ((float4*)y)[(size_t)n * 64 + ycol0 + lane] = acc;
}

// ---------------------------------------------------------------- launch
extern "C" void kernel_launch(void* const* d_in, const int* in_sizes, int n_in,
                              void* d_out, int out_size)
{
    const float* x    = (const float*)d_in[0];
    const void*  ei   = d_in[1];
    const float* Wf   = (const float*)d_in[2];
    const float* Wb   = (const float*)d_in[3];
    const float* bias = (const float*)d_in[4];
    float*       y    = (float*)d_out;

    int M  = in_sizes[0] / DIN;
    int E2 = in_sizes[1];
    int E  = E2 / 2;
    int nb = (M + SB - 1) / SB;

    // one-time side stream + events (resource init only; work is identical every call)
    static cudaStream_t s_pre = nullptr;
    static cudaEvent_t ev_fork = nullptr, ev_pre = nullptr, ev_g = nullptr, ev_b = nullptr;
    static bool tried = false;
    if (!tried) {
        tried = true;
        if (cudaStreamCreateWithFlags(&s_pre, cudaStreamNonBlocking) != cudaSuccess) s_pre = nullptr;
        if (s_pre) {
            cudaEventCreateWithFlags(&ev_fork, cudaEventDisableTiming);
            cudaEventCreateWithFlags(&ev_pre, cudaEventDisableTiming);
            cudaEventCreateWithFlags(&ev_g, cudaEventDisableTiming);
            cudaEventCreateWithFlags(&ev_b, cudaEventDisableTiming);
        }
    }

    cudaStream_t sp = s_pre ? s_pre : (cudaStream_t)0;
    if (s_pre) {
        cudaEventRecord(ev_fork, 0);
        cudaStreamWaitEvent(s_pre, ev_fork, 0);
    }

    // --- preprocessing chain (side stream) ---
    zero_small_kernel<<<(M + 255) / 256, 256, 0, sp>>>(M);
    detect_kernel<<<296, 256, 0, sp>>>((const unsigned*)ei, E2);
    set_flag_kernel<<<1, 1, 0, sp>>>();
    count_deg_kernel<<<(E + 255) / 256, 256, 0, sp>>>(ei, E);
    isr_kernel<<<(M + 255) / 256, 256, 0, sp>>>(M);
    scan_block_sums<<<nb, SB, 0, sp>>>(0, M);
    scan_block_sums<<<nb, SB, 0, sp>>>(1, M);
    scan_bsum<<<1, SB, 0, sp>>>(0, nb);
    scan_bsum<<<1, SB, 0, sp>>>(1, nb);
    scan_final<<<nb, SB, 0, sp>>>(0, M);
    scan_final<<<nb, SB, 0, sp>>>(1, M);
    fill_kernel<<<(E + 255) / 256, 256, 0, sp>>>(ei, E);

    // --- GEMM (main stream, overlaps with preprocessing) ---
    gemm_kernel<<<(M + BM - 1) / BM, 128>>>(x, Wf, Wb, M);

    int gblocks = (M * 32 + 255) / 256;
    if (s_pre) {
        cudaEventRecord(ev_pre, s_pre);
        cudaStreamWaitEvent(0, ev_pre, 0);       // main now has gemm + preproc done
        cudaEventRecord(ev_g, 0);
        cudaStreamWaitEvent(s_pre, ev_g, 0);
        gather_kernel<<<gblocks, 256, 0, 0>>>(0, bias, y, M);
        gather_kernel<<<gblocks, 256, 0, s_pre>>>(1, bias, y, M);
        cudaEventRecord(ev_b, s_pre);
        cudaStreamWaitEvent(0, ev_b, 0);
    } else {
        gather_kernel<<<gblocks, 256>>>(0, bias, y, M);
        gather_kernel<<<gblocks, 256>>>(1, bias, y, M);
    }
}

// round 6
// speedup vs baseline: 1.4014x; 1.2131x over previous
#include <cuda_runtime.h>
#include <cuda_fp16.h>
#include <cstdint>
#include <cstddef>

#define NN_MAX 100000
#define NE_MAX 1600000
#define DIN 256
#define DH 128
#define SB 512

typedef unsigned long long ull;

// ---------------------------------------------------------------- scratch
__device__ __half g_xf[NN_MAX * DH];   // x @ W_f^T  (fp16, 25.6 MB)
__device__ __half g_xb[NN_MAX * DH];   // x @ W_b^T  (fp16, 25.6 MB)
__device__ __half g_xa[NN_MAX * 512];  // x split fp16: [hi(256) | lo(256)]
__device__ __half g_wc[256 * 768];     // W' fp16: [n][hi | hi | lo] over k
__device__ int   g_cnt_c[NN_MAX];
__device__ int   g_cnt_r[NN_MAX];
__device__ float g_isr_in[NN_MAX];
__device__ float g_isr_out[NN_MAX];
__device__ int   g_off_c[NN_MAX];
__device__ int   g_off_r[NN_MAX];
__device__ int   g_cur_c[NN_MAX];
__device__ int   g_cur_r[NN_MAX];
__device__ int   g_bsum_c[SB];
__device__ int   g_bsum_r[SB];
__device__ ull   g_ef[NE_MAX];         // edges sorted by col: (row, w)
__device__ ull   g_eb[NE_MAX];         // edges sorted by row: (col, w)
__device__ int   g_is64;

__device__ __forceinline__ int edge_val(const void* ei, size_t idx) {
    if (g_is64) return (int)((const long long*)ei)[idx];
    return ((const int*)ei)[idx];
}

// ---------------------------------------------------------------- dtype detect (fused flag)
__global__ void detect_flag_kernel(const unsigned* __restrict__ w, int nwords) {
    __shared__ unsigned s;
    if (threadIdx.x == 0) s = 0;
    __syncthreads();
    unsigned acc = 0;
    for (int i = threadIdx.x; i < 16384 && 2 * i + 1 < nwords; i += blockDim.x)
        acc |= w[2 * i + 1];
    #pragma unroll
    for (int o = 16; o > 0; o >>= 1)
        acc |= __shfl_xor_sync(0xffffffffu, acc, o);
    if ((threadIdx.x & 31) == 0 && acc) atomicOr(&s, acc);
    __syncthreads();
    if (threadIdx.x == 0) g_is64 = (s == 0u) ? 1 : 0;
}

__global__ void zero_cnt_kernel(int M) {
    int n = blockIdx.x * blockDim.x + threadIdx.x;
    if (n >= M) return;
    g_cnt_c[n] = 0;
    g_cnt_r[n] = 0;
}

// ---------------------------------------------------------------- degrees
__global__ void count_deg_kernel(const void* __restrict__ ei, int E) {
    int e = blockIdx.x * blockDim.x + threadIdx.x;
    if (e >= E) return;
    int c = edge_val(ei, e);
    int r = edge_val(ei, (size_t)E + e);
    atomicAdd(&g_cnt_c[c], 1);
    atomicAdd(&g_cnt_r[r], 1);
}

__global__ void isr_kernel(int M) {
    int n = blockIdx.x * blockDim.x + threadIdx.x;
    if (n >= M) return;
    g_isr_in[n]  = rsqrtf((float)(g_cnt_c[n] + 1));
    g_isr_out[n] = rsqrtf((float)(g_cnt_r[n] + 1));
}

// ---------------------------------------------------------------- scan (2-level, y = sel)
__global__ void scan_block_sums(int M) {
    int sel = blockIdx.y;
    const int* cnt = sel ? g_cnt_r : g_cnt_c;
    int* bsum = sel ? g_bsum_r : g_bsum_c;
    __shared__ int s[SB];
    int t = threadIdx.x;
    int i = blockIdx.x * SB + t;
    s[t] = (i < M) ? cnt[i] : 0;
    __syncthreads();
    for (int d = SB >> 1; d > 0; d >>= 1) {
        if (t < d) s[t] += s[t + d];
        __syncthreads();
    }
    if (t == 0) bsum[blockIdx.x] = s[0];
}

__global__ void scan_bsum(int nb) {
    int sel = blockIdx.y;
    int* bsum = sel ? g_bsum_r : g_bsum_c;
    __shared__ int s[SB];
    int t = threadIdx.x;
    int v = (t < nb) ? bsum[t] : 0;
    s[t] = v;
    __syncthreads();
    for (int d = 1; d < SB; d <<= 1) {
        int tmp = (t >= d) ? s[t - d] : 0;
        __syncthreads();
        s[t] += tmp;
        __syncthreads();
    }
    if (t < nb) bsum[t] = s[t] - v;
}

__global__ void scan_final(int M) {
    int sel = blockIdx.y;
    const int* cnt = sel ? g_cnt_r : g_cnt_c;
    const int* bsum = sel ? g_bsum_r : g_bsum_c;
    int* off = sel ? g_off_r : g_off_c;
    int* cur = sel ? g_cur_r : g_cur_c;
    __shared__ int s[SB];
    int t = threadIdx.x;
    int i = blockIdx.x * SB + t;
    int v = (i < M) ? cnt[i] : 0;
    s[t] = v;
    __syncthreads();
    for (int d = 1; d < SB; d <<= 1) {
        int tmp = (t >= d) ? s[t - d] : 0;
        __syncthreads();
        s[t] += tmp;
        __syncthreads();
    }
    if (i < M) {
        int ex = s[t] - v + bsum[blockIdx.x];
        off[i] = ex;
        cur[i] = ex;
    }
}

// ---------------------------------------------------------------- fill
__global__ void fill_kernel(const void* __restrict__ ei, int E) {
    int e = blockIdx.x * blockDim.x + threadIdx.x;
    if (e >= E) return;
    int c = edge_val(ei, e);
    int r = edge_val(ei, (size_t)E + e);
    float w = g_isr_out[r] * g_isr_in[c];
    unsigned wb = __float_as_uint(w);
    int pc = atomicAdd(&g_cur_c[c], 1);
    g_ef[pc] = (ull)(unsigned)r | ((ull)wb << 32);
    int pr = atomicAdd(&g_cur_r[r], 1);
    g_eb[pr] = (ull)(unsigned)c | ((ull)wb << 32);
}

// ---------------------------------------------------------------- W' prep (fp16 hi|hi|lo)
__global__ void w_conv_kernel(const float* __restrict__ Wf,
                              const float* __restrict__ Wb) {
    int idx = blockIdx.x * blockDim.x + threadIdx.x;
    if (idx >= 256 * 256) return;
    int n = idx >> 8, k = idx & 255;
    float v = (n < DH) ? Wf[n * DIN + k] : Wb[(n - DH) * DIN + k];
    __half h = __float2half_rn(v);
    __half l = __float2half_rn(v - __half2float(h));
    g_wc[n * 768 + k]       = h;
    g_wc[n * 768 + 256 + k] = h;
    g_wc[n * 768 + 512 + k] = l;
}

// ---------------------------------------------------------------- x split prep (fp16 hi/lo)
__global__ void x_conv_kernel(const float* __restrict__ x, int M) {
    int gid = blockIdx.x * blockDim.x + threadIdx.x;
    if (gid >= M * 64) return;
    int node = gid >> 6, q = gid & 63;
    float4 f = *(const float4*)(x + (size_t)node * DIN + q * 4);
    __half h0 = __float2half_rn(f.x), h1 = __float2half_rn(f.y);
    __half h2 = __float2half_rn(f.z), h3 = __float2half_rn(f.w);
    __half l0 = __float2half_rn(f.x - __half2float(h0));
    __half l1 = __float2half_rn(f.y - __half2float(h1));
    __half l2 = __float2half_rn(f.z - __half2float(h2));
    __half l3 = __float2half_rn(f.w - __half2float(h3));
    __half2 hh0 = __halves2half2(h0, h1), hh1 = __halves2half2(h2, h3);
    __half2 ll0 = __halves2half2(l0, l1), ll1 = __halves2half2(l2, l3);
    uint2 uh = make_uint2(*(unsigned*)&hh0, *(unsigned*)&hh1);
    uint2 ul = make_uint2(*(unsigned*)&ll0, *(unsigned*)&ll1);
    *(uint2*)(g_xa + (size_t)node * 512 + q * 4)       = uh;
    *(uint2*)(g_xa + (size_t)node * 512 + 256 + q * 4) = ul;
}

// ---------------------------------------------------------------- HMMA GEMM
// D[64 x 256] per CTA = A'[64 x 768] x B'[256 x 768]^T (split-fp16 3-term).
// 8 warps: 2(M) x 4(N); warp tile 32 x 64 = 2 x 8 mma(m16n8k16).
// cp.async double-buffered K-chunks of 64.
#define LDA 72
#define LDB 72
#define A_BUF (64 * LDA)            // halves
#define B_BUF (256 * LDB)
#define GEMM_SMEM ((2 * A_BUF + 2 * B_BUF) * 2)

__device__ __forceinline__ void cp16(unsigned daddr, const void* src, unsigned sz) {
    asm volatile("cp.async.ca.shared.global [%0], [%1], 16, %2;"
                 :: "r"(daddr), "l"(src), "r"(sz) : "memory");
}

__global__ __launch_bounds__(256)
void gemm_hmma_kernel(int M)
{
    extern __shared__ __align__(16) __half smem[];
    __half* As = smem;                 // 2 x 64 x 72
    __half* Bs = smem + 2 * A_BUF;     // 2 x 256 x 72

    const int t   = threadIdx.x;
    const int wid = t >> 5;
    const int lid = t & 31;
    const int m0  = blockIdx.x * 64;
    const int wm  = (wid & 1) * 32;    // warp M offset
    const int wn  = (wid >> 1) * 64;   // warp N offset

    float c[2][8][4];
    #pragma unroll
    for (int i = 0; i < 2; ++i)
        #pragma unroll
        for (int j = 0; j < 8; ++j)
            #pragma unroll
            for (int q = 0; q < 4; ++q) c[i][j][q] = 0.f;

    unsigned as_base = (unsigned)__cvta_generic_to_shared(As);
    unsigned bs_base = (unsigned)__cvta_generic_to_shared(Bs);

    auto issue_load = [&](int ch) {
        int buf = ch & 1;
        int seg = ch >> 2;
        int ak = ((seg == 1) ? 256 : 0) + (ch & 3) * 64;   // hi | lo | hi
        int bk = ch * 64;
        // A: 64 rows x 64 halves = 512 x 16B ; 2 per thread
        #pragma unroll
        for (int i = 0; i < 2; ++i) {
            int idx = t + 256 * i;
            int row = idx >> 3, kq = idx & 7;
            const __half* src = g_xa + (size_t)(m0 + row) * 512 + ak + kq * 8;
            unsigned dst = as_base + (buf * A_BUF + row * LDA + kq * 8) * 2;
            cp16(dst, src, (m0 + row) < M ? 16u : 0u);
        }
        // B: 256 rows x 64 halves = 2048 x 16B ; 8 per thread
        #pragma unroll
        for (int i = 0; i < 8; ++i) {
            int idx = t + 256 * i;
            int row = idx >> 3, kq = idx & 7;
            const __half* src = g_wc + (size_t)row * 768 + bk + kq * 8;
            unsigned dst = bs_base + (buf * B_BUF + row * LDB + kq * 8) * 2;
            cp16(dst, src, 16u);
        }
        asm volatile("cp.async.commit_group;" ::: "memory");
    };

    issue_load(0);
    issue_load(1);

    #pragma unroll 1
    for (int ch = 0; ch < 12; ++ch) {
        if (ch == 11) asm volatile("cp.async.wait_group 0;" ::: "memory");
        else          asm volatile("cp.async.wait_group 1;" ::: "memory");
        __syncthreads();

        const __half* A_ = As + (ch & 1) * A_BUF;
        const __half* B_ = Bs + (ch & 1) * B_BUF;

        #pragma unroll
        for (int k16 = 0; k16 < 4; ++k16) {
            int k0 = k16 * 16 + (lid & 3) * 2;
            unsigned a[2][4];
            #pragma unroll
            for (int mt = 0; mt < 2; ++mt) {
                int r = wm + mt * 16 + (lid >> 2);
                a[mt][0] = *(const unsigned*)(A_ + r * LDA + k0);
                a[mt][1] = *(const unsigned*)(A_ + (r + 8) * LDA + k0);
                a[mt][2] = *(const unsigned*)(A_ + r * LDA + k0 + 8);
                a[mt][3] = *(const unsigned*)(A_ + (r + 8) * LDA + k0 + 8);
            }
            #pragma unroll
            for (int nt = 0; nt < 8; ++nt) {
                int nrow = wn + nt * 8 + (lid >> 2);
                unsigned b0 = *(const unsigned*)(B_ + nrow * LDB + k0);
                unsigned b1 = *(const unsigned*)(B_ + nrow * LDB + k0 + 8);
                #pragma unroll
                for (int mt = 0; mt < 2; ++mt) {
                    asm volatile(
                        "mma.sync.aligned.m16n8k16.row.col.f32.f16.f16.f32 "
                        "{%0,%1,%2,%3}, {%4,%5,%6,%7}, {%8,%9}, {%0,%1,%2,%3};"
                        : "+f"(c[mt][nt][0]), "+f"(c[mt][nt][1]),
                          "+f"(c[mt][nt][2]), "+f"(c[mt][nt][3])
                        : "r"(a[mt][0]), "r"(a[mt][1]), "r"(a[mt][2]), "r"(a[mt][3]),
                          "r"(b0), "r"(b1));
                }
            }
        }
        __syncthreads();
        if (ch + 2 < 12) issue_load(ch + 2);
    }

    // epilogue: c[mt][nt][q] -> g_xf / g_xb fp16
    #pragma unroll
    for (int mt = 0; mt < 2; ++mt) {
        #pragma unroll
        for (int half2s = 0; half2s < 2; ++half2s) {   // reg pair (0,1) m, (2,3) m+8
            int node = m0 + wm + mt * 16 + (lid >> 2) + half2s * 8;
            if (node >= M) continue;
            #pragma unroll
            for (int nt = 0; nt < 8; ++nt) {
                int n = wn + nt * 8 + (lid & 3) * 2;
                __half2 h = __floats2half2_rn(c[mt][nt][half2s * 2],
                                              c[mt][nt][half2s * 2 + 1]);
                __half* dst = (n < DH) ? (g_xf + (size_t)node * DH + n)
                                       : (g_xb + (size_t)node * DH + (n - DH));
                *(__half2*)dst = h;
            }
        }
    }
}

// ---------------------------------------------------------------- gather (CSR, fp16 features)
__global__ __launch_bounds__(256)
void gather_kernel(int sel, const float* __restrict__ bias,
                   float* __restrict__ y, int M)
{
    int lane = threadIdx.x & 31;
    int n = (blockIdx.x * blockDim.x + threadIdx.x) >> 5;
    if (n >= M) return;

    const ull* elist    = sel ? g_eb : g_ef;
    const int* off      = sel ? g_off_r : g_off_c;
    const int* cnt      = sel ? g_cnt_r : g_cnt_c;
    const __half* feat  = sel ? g_xb : g_xf;
    int ycol0 = sel ? 32 : 0;

    int beg = off[n];
    int deg = cnt[n];

    float4 acc = ((const float4*)(bias + sel * DH))[lane];
    {
        float ws = g_isr_in[n] * g_isr_out[n];
        uint2 rv = *(const uint2*)(feat + (size_t)n * DH + lane * 4);
        float2 f0 = __half22float2(*(__half2*)&rv.x);
        float2 f1 = __half22float2(*(__half2*)&rv.y);
        acc.x += f0.x * ws; acc.y += f0.y * ws;
        acc.z += f1.x * ws; acc.w += f1.y * ws;
    }

    for (int base = 0; base < deg; base += 32) {
        int e = base + lane;
        ull pk = (e < deg) ? elist[beg + e] : 0ull;
        int m = min(32, deg - base);
        for (int j = 0; j < m; ++j) {
            ull p = __shfl_sync(0xffffffffu, pk, j);
            int src = (int)(unsigned)(p & 0xffffffffu);
            float w = __uint_as_float((unsigned)(p >> 32));
            uint2 rv = *(const uint2*)(feat + (size_t)src * DH + lane * 4);
            float2 f0 = __half22float2(*(__half2*)&rv.x);
            float2 f1 = __half22float2(*(__half2*)&rv.y);
            acc.x += f0.x * w; acc.y += f0.y * w;
            acc.z += f1.x * w; acc.w += f1.y * w;
        }
    }

    ((float4*)y)[(size_t)n * 64 + ycol0 + lane] = acc;
}

// ---------------------------------------------------------------- launch
extern "C" void kernel_launch(void* const* d_in, const int* in_sizes, int n_in,
                              void* d_out, int out_size)
{
    const float* x    = (const float*)d_in[0];
    const void*  ei   = d_in[1];
    const float* Wf   = (const float*)d_in[2];
    const float* Wb   = (const float*)d_in[3];
    const float* bias = (const float*)d_in[4];
    float*       y    = (float*)d_out;

    int M  = in_sizes[0] / DIN;
    int E2 = in_sizes[1];
    int E  = E2 / 2;
    int nb = (M + SB - 1) / SB;

    static cudaStream_t s_pre = nullptr;
    static cudaEvent_t ev_fork = nullptr, ev_pre = nullptr, ev_gm = nullptr, ev_b = nullptr;
    static bool tried = false;
    if (!tried) {
        tried = true;
        cudaFuncSetAttribute(gemm_hmma_kernel,
                             cudaFuncAttributeMaxDynamicSharedMemorySize, GEMM_SMEM);
        if (cudaStreamCreateWithFlags(&s_pre, cudaStreamNonBlocking) != cudaSuccess)
            s_pre = nullptr;
        if (s_pre) {
            cudaEventCreateWithFlags(&ev_fork, cudaEventDisableTiming);
            cudaEventCreateWithFlags(&ev_pre, cudaEventDisableTiming);
            cudaEventCreateWithFlags(&ev_gm, cudaEventDisableTiming);
            cudaEventCreateWithFlags(&ev_b, cudaEventDisableTiming);
        }
    }

    cudaStream_t sp = s_pre ? s_pre : (cudaStream_t)0;
    if (s_pre) {
        cudaEventRecord(ev_fork, 0);
        cudaStreamWaitEvent(s_pre, ev_fork, 0);
    }

    // --- preprocessing chain (side stream) ---
    detect_flag_kernel<<<1, 1024, 0, sp>>>((const unsigned*)ei, E2);
    zero_cnt_kernel<<<(M + 255) / 256, 256, 0, sp>>>(M);
    count_deg_kernel<<<(E + 255) / 256, 256, 0, sp>>>(ei, E);
    isr_kernel<<<(M + 255) / 256, 256, 0, sp>>>(M);
    {
        dim3 g1(nb, 2), g2(1, 2);
        scan_block_sums<<<g1, SB, 0, sp>>>(M);
        scan_bsum<<<g2, SB, 0, sp>>>(nb);
        scan_final<<<g1, SB, 0, sp>>>(M);
    }
    fill_kernel<<<(E + 255) / 256, 256, 0, sp>>>(ei, E);

    // --- GEMM path (main stream, overlaps preprocessing) ---
    w_conv_kernel<<<256, 256>>>(Wf, Wb);
    x_conv_kernel<<<(M * 64 + 255) / 256, 256>>>(x, M);
    gemm_hmma_kernel<<<(M + 63) / 64, 256, GEMM_SMEM>>>(M);

    int gblocks = (M * 32 + 255) / 256;
    if (s_pre) {
        cudaEventRecord(ev_gm, 0);
        cudaEventRecord(ev_pre, s_pre);
        cudaStreamWaitEvent(0, ev_pre, 0);
        cudaStreamWaitEvent(s_pre, ev_gm, 0);
        gather_kernel<<<gblocks, 256, 0, 0>>>(0, bias, y, M);
        gather_kernel<<<gblocks, 256, 0, s_pre>>>(1, bias, y, M);
        cudaEventRecord(ev_b, s_pre);
        cudaStreamWaitEvent(0, ev_b, 0);
    } else {
        gather_kernel<<<gblocks, 256>>>(0, bias, y, M);
        gather_kernel<<<gblocks, 256>>>(1, bias, y, M);
    }
}

// round 7
// speedup vs baseline: 1.9220x; 1.3715x over previous
#include <cuda_runtime.h>
#include <cuda_fp16.h>
#include <cstdint>
#include <cstddef>

#define NN_MAX 100000
#define NE_MAX 1600000
#define DIN 256
#define DH 128
#define SB 512

typedef unsigned long long ull;

// ---------------------------------------------------------------- scratch
__device__ __half g_xf[NN_MAX * DH];   // x @ W_f^T  (fp16, 25.6 MB)
__device__ __half g_xb[NN_MAX * DH];   // x @ W_b^T  (fp16, 25.6 MB)
__device__ __half g_xa[NN_MAX * DIN];  // x as fp16 (51.2 MB)
__device__ __half g_wc[256 * DIN];     // W' fp16 [n][k]  (Wf rows 0-127, Wb 128-255)
__device__ int   g_cnt_c[NN_MAX];
__device__ int   g_cnt_r[NN_MAX];
__device__ float g_isr_in[NN_MAX];
__device__ float g_isr_out[NN_MAX];
__device__ int   g_off_c[NN_MAX];
__device__ int   g_off_r[NN_MAX];
__device__ int   g_cur_c[NN_MAX];
__device__ int   g_cur_r[NN_MAX];
__device__ int   g_bsum_c[SB];
__device__ int   g_bsum_r[SB];
__device__ ull   g_ef[NE_MAX];         // edges sorted by col: (row, w)
__device__ ull   g_eb[NE_MAX];         // edges sorted by row: (col, w)
__device__ int   g_is64;

__device__ __forceinline__ int edge_val(const void* ei, size_t idx) {
    if (g_is64) return (int)((const long long*)ei)[idx];
    return ((const int*)ei)[idx];
}

// ---------------------------------------------------------------- dtype detect (fused flag)
__global__ void detect_flag_kernel(const unsigned* __restrict__ w, int nwords) {
    __shared__ unsigned s;
    if (threadIdx.x == 0) s = 0;
    __syncthreads();
    unsigned acc = 0;
    for (int i = threadIdx.x; i < 16384 && 2 * i + 1 < nwords; i += blockDim.x)
        acc |= w[2 * i + 1];
    #pragma unroll
    for (int o = 16; o > 0; o >>= 1)
        acc |= __shfl_xor_sync(0xffffffffu, acc, o);
    if ((threadIdx.x & 31) == 0 && acc) atomicOr(&s, acc);
    __syncthreads();
    if (threadIdx.x == 0) g_is64 = (s == 0u) ? 1 : 0;
}

__global__ void zero_cnt_kernel(int M) {
    int n = blockIdx.x * blockDim.x + threadIdx.x;
    if (n >= M) return;
    g_cnt_c[n] = 0;
    g_cnt_r[n] = 0;
}

// ---------------------------------------------------------------- degrees
__global__ void count_deg_kernel(const void* __restrict__ ei, int E) {
    int e = blockIdx.x * blockDim.x + threadIdx.x;
    if (e >= E) return;
    int c = edge_val(ei, e);
    int r = edge_val(ei, (size_t)E + e);
    atomicAdd(&g_cnt_c[c], 1);
    atomicAdd(&g_cnt_r[r], 1);
}

__global__ void isr_kernel(int M) {
    int n = blockIdx.x * blockDim.x + threadIdx.x;
    if (n >= M) return;
    g_isr_in[n]  = rsqrtf((float)(g_cnt_c[n] + 1));
    g_isr_out[n] = rsqrtf((float)(g_cnt_r[n] + 1));
}

// ---------------------------------------------------------------- scan (2-level, y = sel)
__global__ void scan_block_sums(int M) {
    int sel = blockIdx.y;
    const int* cnt = sel ? g_cnt_r : g_cnt_c;
    int* bsum = sel ? g_bsum_r : g_bsum_c;
    __shared__ int s[SB];
    int t = threadIdx.x;
    int i = blockIdx.x * SB + t;
    s[t] = (i < M) ? cnt[i] : 0;
    __syncthreads();
    for (int d = SB >> 1; d > 0; d >>= 1) {
        if (t < d) s[t] += s[t + d];
        __syncthreads();
    }
    if (t == 0) bsum[blockIdx.x] = s[0];
}

__global__ void scan_bsum(int nb) {
    int sel = blockIdx.y;
    int* bsum = sel ? g_bsum_r : g_bsum_c;
    __shared__ int s[SB];
    int t = threadIdx.x;
    int v = (t < nb) ? bsum[t] : 0;
    s[t] = v;
    __syncthreads();
    for (int d = 1; d < SB; d <<= 1) {
        int tmp = (t >= d) ? s[t - d] : 0;
        __syncthreads();
        s[t] += tmp;
        __syncthreads();
    }
    if (t < nb) bsum[t] = s[t] - v;
}

__global__ void scan_final(int M) {
    int sel = blockIdx.y;
    const int* cnt = sel ? g_cnt_r : g_cnt_c;
    const int* bsum = sel ? g_bsum_r : g_bsum_c;
    int* off = sel ? g_off_r : g_off_c;
    int* cur = sel ? g_cur_r : g_cur_c;
    __shared__ int s[SB];
    int t = threadIdx.x;
    int i = blockIdx.x * SB + t;
    int v = (i < M) ? cnt[i] : 0;
    s[t] = v;
    __syncthreads();
    for (int d = 1; d < SB; d <<= 1) {
        int tmp = (t >= d) ? s[t - d] : 0;
        __syncthreads();
        s[t] += tmp;
        __syncthreads();
    }
    if (i < M) {
        int ex = s[t] - v + bsum[blockIdx.x];
        off[i] = ex;
        cur[i] = ex;
    }
}

// ---------------------------------------------------------------- fill
__global__ void fill_kernel(const void* __restrict__ ei, int E) {
    int e = blockIdx.x * blockDim.x + threadIdx.x;
    if (e >= E) return;
    int c = edge_val(ei, e);
    int r = edge_val(ei, (size_t)E + e);
    float w = g_isr_out[r] * g_isr_in[c];
    unsigned wb = __float_as_uint(w);
    int pc = atomicAdd(&g_cur_c[c], 1);
    g_ef[pc] = (ull)(unsigned)r | ((ull)wb << 32);
    int pr = atomicAdd(&g_cur_r[r], 1);
    g_eb[pr] = (ull)(unsigned)c | ((ull)wb << 32);
}

// ---------------------------------------------------------------- W' prep (fp16)
__global__ void w_conv_kernel(const float* __restrict__ Wf,
                              const float* __restrict__ Wb) {
    int idx = blockIdx.x * blockDim.x + threadIdx.x;
    if (idx >= 256 * 256) return;
    int n = idx >> 8, k = idx & 255;
    float v = (n < DH) ? Wf[n * DIN + k] : Wb[(n - DH) * DIN + k];
    g_wc[n * DIN + k] = __float2half_rn(v);
}

// ---------------------------------------------------------------- x prep (fp16)
__global__ void x_conv_kernel(const float* __restrict__ x, int M) {
    int gid = blockIdx.x * blockDim.x + threadIdx.x;
    if (gid >= M * 64) return;
    int node = gid >> 6, q = gid & 63;
    float4 f = *(const float4*)(x + (size_t)node * DIN + q * 4);
    __half2 h0 = __floats2half2_rn(f.x, f.y);
    __half2 h1 = __floats2half2_rn(f.z, f.w);
    uint2 u = make_uint2(*(unsigned*)&h0, *(unsigned*)&h1);
    *(uint2*)(g_xa + (size_t)node * DIN + q * 4) = u;
}

// ---------------------------------------------------------------- HMMA GEMM
// D[64 x 256] per CTA = A[64 x 256] x B[256 x 256]^T (plain fp16, fp32 accum).
// 8 warps: 2(M) x 4(N); warp tile 32 x 64 = 2 x 8 mma(m16n8k16).
// cp.async double-buffered K-chunks of 64.
#define LDA 72
#define LDB 72
#define A_BUF (64 * LDA)            // halves
#define B_BUF (256 * LDB)
#define GEMM_SMEM ((2 * A_BUF + 2 * B_BUF) * 2)
#define NCHUNK 4

__device__ __forceinline__ void cp16(unsigned daddr, const void* src, unsigned sz) {
    asm volatile("cp.async.ca.shared.global [%0], [%1], 16, %2;"
                 :: "r"(daddr), "l"(src), "r"(sz) : "memory");
}

__global__ __launch_bounds__(256)
void gemm_hmma_kernel(int M)
{
    extern __shared__ __align__(16) __half smem[];
    __half* As = smem;                 // 2 x 64 x 72
    __half* Bs = smem + 2 * A_BUF;     // 2 x 256 x 72

    const int t   = threadIdx.x;
    const int wid = t >> 5;
    const int lid = t & 31;
    const int m0  = blockIdx.x * 64;
    const int wm  = (wid & 1) * 32;    // warp M offset
    const int wn  = (wid >> 1) * 64;   // warp N offset

    float c[2][8][4];
    #pragma unroll
    for (int i = 0; i < 2; ++i)
        #pragma unroll
        for (int j = 0; j < 8; ++j)
            #pragma unroll
            for (int q = 0; q < 4; ++q) c[i][j][q] = 0.f;

    unsigned as_base = (unsigned)__cvta_generic_to_shared(As);
    unsigned bs_base = (unsigned)__cvta_generic_to_shared(Bs);

    auto issue_load = [&](int ch) {
        int buf = ch & 1;
        int k0 = ch * 64;
        // A: 64 rows x 64 halves = 512 x 16B ; 2 per thread
        #pragma unroll
        for (int i = 0; i < 2; ++i) {
            int idx = t + 256 * i;
            int row = idx >> 3, kq = idx & 7;
            const __half* src = g_xa + (size_t)(m0 + row) * DIN + k0 + kq * 8;
            unsigned dst = as_base + (buf * A_BUF + row * LDA + kq * 8) * 2;
            cp16(dst, src, (m0 + row) < M ? 16u : 0u);
        }
        // B: 256 rows x 64 halves = 2048 x 16B ; 8 per thread
        #pragma unroll
        for (int i = 0; i < 8; ++i) {
            int idx = t + 256 * i;
            int row = idx >> 3, kq = idx & 7;
            const __half* src = g_wc + (size_t)row * DIN + k0 + kq * 8;
            unsigned dst = bs_base + (buf * B_BUF + row * LDB + kq * 8) * 2;
            cp16(dst, src, 16u);
        }
        asm volatile("cp.async.commit_group;" ::: "memory");
    };

    issue_load(0);
    issue_load(1);

    #pragma unroll 1
    for (int ch = 0; ch < NCHUNK; ++ch) {
        if (ch == NCHUNK - 1) asm volatile("cp.async.wait_group 0;" ::: "memory");
        else                  asm volatile("cp.async.wait_group 1;" ::: "memory");
        __syncthreads();

        const __half* A_ = As + (ch & 1) * A_BUF;
        const __half* B_ = Bs + (ch & 1) * B_BUF;

        #pragma unroll
        for (int k16 = 0; k16 < 4; ++k16) {
            int k0 = k16 * 16 + (lid & 3) * 2;
            unsigned a[2][4];
            #pragma unroll
            for (int mt = 0; mt < 2; ++mt) {
                int r = wm + mt * 16 + (lid >> 2);
                a[mt][0] = *(const unsigned*)(A_ + r * LDA + k0);
                a[mt][1] = *(const unsigned*)(A_ + (r + 8) * LDA + k0);
                a[mt][2] = *(const unsigned*)(A_ + r * LDA + k0 + 8);
                a[mt][3] = *(const unsigned*)(A_ + (r + 8) * LDA + k0 + 8);
            }
            #pragma unroll
            for (int nt = 0; nt < 8; ++nt) {
                int nrow = wn + nt * 8 + (lid >> 2);
                unsigned b0 = *(const unsigned*)(B_ + nrow * LDB + k0);
                unsigned b1 = *(const unsigned*)(B_ + nrow * LDB + k0 + 8);
                #pragma unroll
                for (int mt = 0; mt < 2; ++mt) {
                    asm volatile(
                        "mma.sync.aligned.m16n8k16.row.col.f32.f16.f16.f32 "
                        "{%0,%1,%2,%3}, {%4,%5,%6,%7}, {%8,%9}, {%0,%1,%2,%3};"
                        : "+f"(c[mt][nt][0]), "+f"(c[mt][nt][1]),
                          "+f"(c[mt][nt][2]), "+f"(c[mt][nt][3])
                        : "r"(a[mt][0]), "r"(a[mt][1]), "r"(a[mt][2]), "r"(a[mt][3]),
                          "r"(b0), "r"(b1));
                }
            }
        }
        __syncthreads();
        if (ch + 2 < NCHUNK) issue_load(ch + 2);
    }

    // epilogue: c[mt][nt][q] -> g_xf / g_xb fp16
    #pragma unroll
    for (int mt = 0; mt < 2; ++mt) {
        #pragma unroll
        for (int half2s = 0; half2s < 2; ++half2s) {
            int node = m0 + wm + mt * 16 + (lid >> 2) + half2s * 8;
            if (node >= M) continue;
            #pragma unroll
            for (int nt = 0; nt < 8; ++nt) {
                int n = wn + nt * 8 + (lid & 3) * 2;
                __half2 h = __floats2half2_rn(c[mt][nt][half2s * 2],
                                              c[mt][nt][half2s * 2 + 1]);
                __half* dst = (n < DH) ? (g_xf + (size_t)node * DH + n)
                                       : (g_xb + (size_t)node * DH + (n - DH));
                *(__half2*)dst = h;
            }
        }
    }
}

// ---------------------------------------------------------------- gather (CSR, fp16 features)
__global__ __launch_bounds__(256)
void gather_kernel(int sel, const float* __restrict__ bias,
                   float* __restrict__ y, int M)
{
    int lane = threadIdx.x & 31;
    int n = (blockIdx.x * blockDim.x + threadIdx.x) >> 5;
    if (n >= M) return;

    const ull* elist    = sel ? g_eb : g_ef;
    const int* off      = sel ? g_off_r : g_off_c;
    const int* cnt      = sel ? g_cnt_r : g_cnt_c;
    const __half* feat  = sel ? g_xb : g_xf;
    int ycol0 = sel ? 32 : 0;

    int beg = off[n];
    int deg = cnt[n];

    float4 acc = ((const float4*)(bias + sel * DH))[lane];
    {
        float ws = g_isr_in[n] * g_isr_out[n];
        uint2 rv = *(const uint2*)(feat + (size_t)n * DH + lane * 4);
        float2 f0 = __half22float2(*(__half2*)&rv.x);
        float2 f1 = __half22float2(*(__half2*)&rv.y);
        acc.x += f0.x * ws; acc.y += f0.y * ws;
        acc.z += f1.x * ws; acc.w += f1.y * ws;
    }

    for (int base = 0; base < deg; base += 32) {
        int e = base + lane;
        ull pk = (e < deg) ? __ldg(elist + beg + e) : 0ull;
        int m = min(32, deg - base);
        for (int j = 0; j < m; ++j) {
            ull p = __shfl_sync(0xffffffffu, pk, j);
            int src = (int)(unsigned)(p & 0xffffffffu);
            float w = __uint_as_float((unsigned)(p >> 32));
            uint2 rv = __ldg((const uint2*)(feat + (size_t)src * DH) + lane);
            float2 f0 = __half22float2(*(__half2*)&rv.x);
            float2 f1 = __half22float2(*(__half2*)&rv.y);
            acc.x += f0.x * w; acc.y += f0.y * w;
            acc.z += f1.x * w; acc.w += f1.y * w;
        }
    }

    ((float4*)y)[(size_t)n * 64 + ycol0 + lane] = acc;
}

// ---------------------------------------------------------------- launch
extern "C" void kernel_launch(void* const* d_in, const int* in_sizes, int n_in,
                              void* d_out, int out_size)
{
    const float* x    = (const float*)d_in[0];
    const void*  ei   = d_in[1];
    const float* Wf   = (const float*)d_in[2];
    const float* Wb   = (const float*)d_in[3];
    const float* bias = (const float*)d_in[4];
    float*       y    = (float*)d_out;

    int M  = in_sizes[0] / DIN;
    int E2 = in_sizes[1];
    int E  = E2 / 2;
    int nb = (M + SB - 1) / SB;

    static cudaStream_t s_pre = nullptr;
    static cudaEvent_t ev_fork = nullptr, ev_pre = nullptr, ev_gm = nullptr, ev_b = nullptr;
    static bool tried = false;
    if (!tried) {
        tried = true;
        cudaFuncSetAttribute(gemm_hmma_kernel,
                             cudaFuncAttributeMaxDynamicSharedMemorySize, GEMM_SMEM);
        if (cudaStreamCreateWithFlags(&s_pre, cudaStreamNonBlocking) != cudaSuccess)
            s_pre = nullptr;
        if (s_pre) {
            cudaEventCreateWithFlags(&ev_fork, cudaEventDisableTiming);
            cudaEventCreateWithFlags(&ev_pre, cudaEventDisableTiming);
            cudaEventCreateWithFlags(&ev_gm, cudaEventDisableTiming);
            cudaEventCreateWithFlags(&ev_b, cudaEventDisableTiming);
        }
    }

    cudaStream_t sp = s_pre ? s_pre : (cudaStream_t)0;
    if (s_pre) {
        cudaEventRecord(ev_fork, 0);
        cudaStreamWaitEvent(s_pre, ev_fork, 0);
    }

    // --- preprocessing chain (side stream) ---
    detect_flag_kernel<<<1, 1024, 0, sp>>>((const unsigned*)ei, E2);
    zero_cnt_kernel<<<(M + 255) / 256, 256, 0, sp>>>(M);
    count_deg_kernel<<<(E + 255) / 256, 256, 0, sp>>>(ei, E);
    isr_kernel<<<(M + 255) / 256, 256, 0, sp>>>(M);
    {
        dim3 g1(nb, 2), g2(1, 2);
        scan_block_sums<<<g1, SB, 0, sp>>>(M);
        scan_bsum<<<g2, SB, 0, sp>>>(nb);
        scan_final<<<g1, SB, 0, sp>>>(M);
    }
    fill_kernel<<<(E + 255) / 256, 256, 0, sp>>>(ei, E);

    // --- GEMM path (main stream, overlaps preprocessing) ---
    w_conv_kernel<<<256, 256>>>(Wf, Wb);
    x_conv_kernel<<<(M * 64 + 255) / 256, 256>>>(x, M);
    gemm_hmma_kernel<<<(M + 63) / 64, 256, GEMM_SMEM>>>(M);

    int gblocks = (M * 32 + 255) / 256;
    if (s_pre) {
        cudaEventRecord(ev_gm, 0);
        cudaEventRecord(ev_pre, s_pre);
        cudaStreamWaitEvent(0, ev_pre, 0);
        cudaStreamWaitEvent(s_pre, ev_gm, 0);
        gather_kernel<<<gblocks, 256, 0, 0>>>(0, bias, y, M);
        gather_kernel<<<gblocks, 256, 0, s_pre>>>(1, bias, y, M);
        cudaEventRecord(ev_b, s_pre);
        cudaStreamWaitEvent(0, ev_b, 0);
    } else {
        gather_kernel<<<gblocks, 256>>>(0, bias, y, M);
        gather_kernel<<<gblocks, 256>>>(1, bias, y, M);
    }
}

// round 8
// speedup vs baseline: 2.1334x; 1.1100x over previous
#include <cuda_runtime.h>
#include <cuda_fp16.h>
#include <cstdint>
#include <cstddef>

#define NN_MAX 100000
#define NE_MAX 1600000
#define DIN 256
#define DH 128
#define SB 512

typedef unsigned long long ull;

// ---------------------------------------------------------------- scratch
__device__ __half g_xf[NN_MAX * DH];   // isr_out[n] * (x @ W_f^T)[n]  (fp16)
__device__ __half g_xb[NN_MAX * DH];   // isr_in[n]  * (x @ W_b^T)[n]  (fp16)
__device__ __half g_xa[NN_MAX * DIN];  // x as fp16
__device__ __half g_wc[256 * DIN];     // W fp16 [n][k] (Wf rows 0-127, Wb 128-255)
__device__ int   g_cnt_c[NN_MAX];
__device__ int   g_cnt_r[NN_MAX];
__device__ float g_isr_in[NN_MAX];
__device__ float g_isr_out[NN_MAX];
__device__ int   g_off_c[NN_MAX];
__device__ int   g_off_r[NN_MAX];
__device__ int   g_cur_c[NN_MAX];
__device__ int   g_cur_r[NN_MAX];
__device__ int   g_bsum_c[SB];
__device__ int   g_bsum_r[SB];
__device__ int   g_efi[NE_MAX];        // edges sorted by col: src=row
__device__ int   g_ebi[NE_MAX];        // edges sorted by row: src=col
__device__ int   g_is64;

__device__ __forceinline__ int edge_val(const void* ei, size_t idx) {
    if (g_is64) return (int)((const long long*)ei)[idx];
    return ((const int*)ei)[idx];
}

// ---------------------------------------------------------------- dtype detect + zero
__global__ void detect_flag_kernel(const unsigned* __restrict__ w, int nwords) {
    __shared__ unsigned s;
    if (threadIdx.x == 0) s = 0;
    __syncthreads();
    unsigned acc = 0;
    for (int i = threadIdx.x; i < 16384 && 2 * i + 1 < nwords; i += blockDim.x)
        acc |= w[2 * i + 1];
    #pragma unroll
    for (int o = 16; o > 0; o >>= 1)
        acc |= __shfl_xor_sync(0xffffffffu, acc, o);
    if ((threadIdx.x & 31) == 0 && acc) atomicOr(&s, acc);
    __syncthreads();
    if (threadIdx.x == 0) g_is64 = (s == 0u) ? 1 : 0;
}

__global__ void zero_cnt_kernel(int M) {
    int n = blockIdx.x * blockDim.x + threadIdx.x;
    if (n >= M) return;
    g_cnt_c[n] = 0;
    g_cnt_r[n] = 0;
}

// ---------------------------------------------------------------- degrees + isr
__global__ void count_deg_kernel(const void* __restrict__ ei, int E) {
    int e = blockIdx.x * blockDim.x + threadIdx.x;
    if (e >= E) return;
    int c = edge_val(ei, e);
    int r = edge_val(ei, (size_t)E + e);
    atomicAdd(&g_cnt_c[c], 1);
    atomicAdd(&g_cnt_r[r], 1);
}

__global__ void isr_kernel(int M) {
    int n = blockIdx.x * blockDim.x + threadIdx.x;
    if (n >= M) return;
    g_isr_in[n]  = rsqrtf((float)(g_cnt_c[n] + 1));
    g_isr_out[n] = rsqrtf((float)(g_cnt_r[n] + 1));
}

// ---------------------------------------------------------------- scan (2-level, per side)
__global__ void scan_block_sums(int sel, int M) {
    const int* cnt = sel ? g_cnt_r : g_cnt_c;
    int* bsum = sel ? g_bsum_r : g_bsum_c;
    __shared__ int s[SB];
    int t = threadIdx.x;
    int i = blockIdx.x * SB + t;
    s[t] = (i < M) ? cnt[i] : 0;
    __syncthreads();
    for (int d = SB >> 1; d > 0; d >>= 1) {
        if (t < d) s[t] += s[t + d];
        __syncthreads();
    }
    if (t == 0) bsum[blockIdx.x] = s[0];
}

__global__ void scan_bsum(int sel, int nb) {
    int* bsum = sel ? g_bsum_r : g_bsum_c;
    __shared__ int s[SB];
    int t = threadIdx.x;
    int v = (t < nb) ? bsum[t] : 0;
    s[t] = v;
    __syncthreads();
    for (int d = 1; d < SB; d <<= 1) {
        int tmp = (t >= d) ? s[t - d] : 0;
        __syncthreads();
        s[t] += tmp;
        __syncthreads();
    }
    if (t < nb) bsum[t] = s[t] - v;
}

__global__ void scan_final(int sel, int M) {
    const int* cnt = sel ? g_cnt_r : g_cnt_c;
    const int* bsum = sel ? g_bsum_r : g_bsum_c;
    int* off = sel ? g_off_r : g_off_c;
    int* cur = sel ? g_cur_r : g_cur_c;
    __shared__ int s[SB];
    int t = threadIdx.x;
    int i = blockIdx.x * SB + t;
    int v = (i < M) ? cnt[i] : 0;
    s[t] = v;
    __syncthreads();
    for (int d = 1; d < SB; d <<= 1) {
        int tmp = (t >= d) ? s[t - d] : 0;
        __syncthreads();
        s[t] += tmp;
        __syncthreads();
    }
    if (i < M) {
        int ex = s[t] - v + bsum[blockIdx.x];
        off[i] = ex;
        cur[i] = ex;
    }
}

// ---------------------------------------------------------------- fill (per side, no weights)
__global__ void fill_c_kernel(const void* __restrict__ ei, int E) {
    int e = blockIdx.x * blockDim.x + threadIdx.x;
    if (e >= E) return;
    int c = edge_val(ei, e);
    int r = edge_val(ei, (size_t)E + e);
    int pc = atomicAdd(&g_cur_c[c], 1);
    g_efi[pc] = r;
}

__global__ void fill_r_kernel(const void* __restrict__ ei, int E) {
    int e = blockIdx.x * blockDim.x + threadIdx.x;
    if (e >= E) return;
    int c = edge_val(ei, e);
    int r = edge_val(ei, (size_t)E + e);
    int pr = atomicAdd(&g_cur_r[r], 1);
    g_ebi[pr] = c;
}

// ---------------------------------------------------------------- W / x prep (fp16)
__global__ void w_conv_kernel(const float* __restrict__ Wf,
                              const float* __restrict__ Wb) {
    int idx = blockIdx.x * blockDim.x + threadIdx.x;
    if (idx >= 256 * 256) return;
    int n = idx >> 8, k = idx & 255;
    float v = (n < DH) ? Wf[n * DIN + k] : Wb[(n - DH) * DIN + k];
    g_wc[n * DIN + k] = __float2half_rn(v);
}

__global__ void x_conv_kernel(const float* __restrict__ x, int M) {
    int gid = blockIdx.x * blockDim.x + threadIdx.x;
    if (gid >= M * 64) return;
    int node = gid >> 6, q = gid & 63;
    float4 f = *(const float4*)(x + (size_t)node * DIN + q * 4);
    __half2 h0 = __floats2half2_rn(f.x, f.y);
    __half2 h1 = __floats2half2_rn(f.z, f.w);
    uint2 u = make_uint2(*(unsigned*)&h0, *(unsigned*)&h1);
    *(uint2*)(g_xa + (size_t)node * DIN + q * 4) = u;
}

// ---------------------------------------------------------------- HMMA GEMM
// D[64 x 256] per CTA = A[64 x 256] x B[256 x 256]^T (fp16 in, fp32 accum).
// Epilogue scales rows: xf by isr_out[node], xb by isr_in[node].
#define LDA 72
#define LDB 72
#define A_BUF (64 * LDA)
#define B_BUF (256 * LDB)
#define GEMM_SMEM ((2 * A_BUF + 2 * B_BUF) * 2)
#define NCHUNK 4

__device__ __forceinline__ void cp16(unsigned daddr, const void* src, unsigned sz) {
    asm volatile("cp.async.ca.shared.global [%0], [%1], 16, %2;"
                 :: "r"(daddr), "l"(src), "r"(sz) : "memory");
}

__global__ __launch_bounds__(256)
void gemm_hmma_kernel(int M)
{
    extern __shared__ __align__(16) __half smem[];
    __half* As = smem;
    __half* Bs = smem + 2 * A_BUF;

    const int t   = threadIdx.x;
    const int wid = t >> 5;
    const int lid = t & 31;
    const int m0  = blockIdx.x * 64;
    const int wm  = (wid & 1) * 32;
    const int wn  = (wid >> 1) * 64;

    float c[2][8][4];
    #pragma unroll
    for (int i = 0; i < 2; ++i)
        #pragma unroll
        for (int j = 0; j < 8; ++j)
            #pragma unroll
            for (int q = 0; q < 4; ++q) c[i][j][q] = 0.f;

    unsigned as_base = (unsigned)__cvta_generic_to_shared(As);
    unsigned bs_base = (unsigned)__cvta_generic_to_shared(Bs);

    auto issue_load = [&](int ch) {
        int buf = ch & 1;
        int k0 = ch * 64;
        #pragma unroll
        for (int i = 0; i < 2; ++i) {
            int idx = t + 256 * i;
            int row = idx >> 3, kq = idx & 7;
            const __half* src = g_xa + (size_t)(m0 + row) * DIN + k0 + kq * 8;
            unsigned dst = as_base + (buf * A_BUF + row * LDA + kq * 8) * 2;
            cp16(dst, src, (m0 + row) < M ? 16u : 0u);
        }
        #pragma unroll
        for (int i = 0; i < 8; ++i) {
            int idx = t + 256 * i;
            int row = idx >> 3, kq = idx & 7;
            const __half* src = g_wc + (size_t)row * DIN + k0 + kq * 8;
            unsigned dst = bs_base + (buf * B_BUF + row * LDB + kq * 8) * 2;
            cp16(dst, src, 16u);
        }
        asm volatile("cp.async.commit_group;" ::: "memory");
    };

    issue_load(0);
    issue_load(1);

    #pragma unroll 1
    for (int ch = 0; ch < NCHUNK; ++ch) {
        if (ch == NCHUNK - 1) asm volatile("cp.async.wait_group 0;" ::: "memory");
        else                  asm volatile("cp.async.wait_group 1;" ::: "memory");
        __syncthreads();

        const __half* A_ = As + (ch & 1) * A_BUF;
        const __half* B_ = Bs + (ch & 1) * B_BUF;

        #pragma unroll
        for (int k16 = 0; k16 < 4; ++k16) {
            int k0 = k16 * 16 + (lid & 3) * 2;
            unsigned a[2][4];
            #pragma unroll
            for (int mt = 0; mt < 2; ++mt) {
                int r = wm + mt * 16 + (lid >> 2);
                a[mt][0] = *(const unsigned*)(A_ + r * LDA + k0);
                a[mt][1] = *(const unsigned*)(A_ + (r + 8) * LDA + k0);
                a[mt][2] = *(const unsigned*)(A_ + r * LDA + k0 + 8);
                a[mt][3] = *(const unsigned*)(A_ + (r + 8) * LDA + k0 + 8);
            }
            #pragma unroll
            for (int nt = 0; nt < 8; ++nt) {
                int nrow = wn + nt * 8 + (lid >> 2);
                unsigned b0 = *(const unsigned*)(B_ + nrow * LDB + k0);
                unsigned b1 = *(const unsigned*)(B_ + nrow * LDB + k0 + 8);
                #pragma unroll
                for (int mt = 0; mt < 2; ++mt) {
                    asm volatile(
                        "mma.sync.aligned.m16n8k16.row.col.f32.f16.f16.f32 "
                        "{%0,%1,%2,%3}, {%4,%5,%6,%7}, {%8,%9}, {%0,%1,%2,%3};"
                        : "+f"(c[mt][nt][0]), "+f"(c[mt][nt][1]),
                          "+f"(c[mt][nt][2]), "+f"(c[mt][nt][3])
                        : "r"(a[mt][0]), "r"(a[mt][1]), "r"(a[mt][2]), "r"(a[mt][3]),
                          "r"(b0), "r"(b1));
                }
            }
        }
        __syncthreads();
        if (ch + 2 < NCHUNK) issue_load(ch + 2);
    }

    // epilogue: scale rows (fwd: isr_out, bwd: isr_in) -> fp16 tables
    const float* scale_arr = (wn < DH) ? g_isr_out : g_isr_in;
    #pragma unroll
    for (int mt = 0; mt < 2; ++mt) {
        #pragma unroll
        for (int half2s = 0; half2s < 2; ++half2s) {
            int node = m0 + wm + mt * 16 + (lid >> 2) + half2s * 8;
            if (node >= M) continue;
            float sc = scale_arr[node];
            #pragma unroll
            for (int nt = 0; nt < 8; ++nt) {
                int n = wn + nt * 8 + (lid & 3) * 2;
                __half2 h = __floats2half2_rn(sc * c[mt][nt][half2s * 2],
                                              sc * c[mt][nt][half2s * 2 + 1]);
                __half* dst = (n < DH) ? (g_xf + (size_t)node * DH + n)
                                       : (g_xb + (size_t)node * DH + (n - DH));
                *(__half2*)dst = h;
            }
        }
    }
}

// ---------------------------------------------------------------- gather (CSR, no weights)
// y[n, fwd]  = bias_f + isr_in[n]  * (feat_f[n] + sum feat_f[src])
// y[n, bwd]  = bias_b + isr_out[n] * (feat_b[n] + sum feat_b[src])
__global__ __launch_bounds__(256)
void gather_kernel(int sel, const float* __restrict__ bias,
                   float* __restrict__ y, int M)
{
    int lane = threadIdx.x & 31;
    int n = (blockIdx.x * blockDim.x + threadIdx.x) >> 5;
    if (n >= M) return;

    const int* elist   = sel ? g_ebi : g_efi;
    const int* off     = sel ? g_off_r : g_off_c;
    const int* cnt     = sel ? g_cnt_r : g_cnt_c;
    const __half* feat = sel ? g_xb : g_xf;
    float nscale = sel ? g_isr_out[n] : g_isr_in[n];
    int ycol0 = sel ? 32 : 0;

    int beg = off[n];
    int deg = cnt[n];

    float4 acc;
    {
        uint2 rv = *(const uint2*)(feat + (size_t)n * DH + lane * 4);
        float2 f0 = __half22float2(*(__half2*)&rv.x);
        float2 f1 = __half22float2(*(__half2*)&rv.y);
        acc = make_float4(f0.x, f0.y, f1.x, f1.y);
    }

    for (int base = 0; base < deg; base += 32) {
        int e = base + lane;
        int src = (e < deg) ? __ldg(elist + beg + e) : 0;
        int m = min(32, deg - base);
        int j = 0;
        for (; j + 4 <= m; j += 4) {
            int s0 = __shfl_sync(0xffffffffu, src, j);
            int s1 = __shfl_sync(0xffffffffu, src, j + 1);
            int s2 = __shfl_sync(0xffffffffu, src, j + 2);
            int s3 = __shfl_sync(0xffffffffu, src, j + 3);
            uint2 v0 = __ldg((const uint2*)(feat + (size_t)s0 * DH) + lane);
            uint2 v1 = __ldg((const uint2*)(feat + (size_t)s1 * DH) + lane);
            uint2 v2 = __ldg((const uint2*)(feat + (size_t)s2 * DH) + lane);
            uint2 v3 = __ldg((const uint2*)(feat + (size_t)s3 * DH) + lane);
            float2 a0 = __half22float2(*(__half2*)&v0.x);
            float2 a1 = __half22float2(*(__half2*)&v0.y);
            acc.x += a0.x; acc.y += a0.y; acc.z += a1.x; acc.w += a1.y;
            a0 = __half22float2(*(__half2*)&v1.x);
            a1 = __half22float2(*(__half2*)&v1.y);
            acc.x += a0.x; acc.y += a0.y; acc.z += a1.x; acc.w += a1.y;
            a0 = __half22float2(*(__half2*)&v2.x);
            a1 = __half22float2(*(__half2*)&v2.y);
            acc.x += a0.x; acc.y += a0.y; acc.z += a1.x; acc.w += a1.y;
            a0 = __half22float2(*(__half2*)&v3.x);
            a1 = __half22float2(*(__half2*)&v3.y);
            acc.x += a0.x; acc.y += a0.y; acc.z += a1.x; acc.w += a1.y;
        }
        for (; j < m; ++j) {
            int s0 = __shfl_sync(0xffffffffu, src, j);
            uint2 v0 = __ldg((const uint2*)(feat + (size_t)s0 * DH) + lane);
            float2 a0 = __half22float2(*(__half2*)&v0.x);
            float2 a1 = __half22float2(*(__half2*)&v0.y);
            acc.x += a0.x; acc.y += a0.y; acc.z += a1.x; acc.w += a1.y;
        }
    }

    float4 b = ((const float4*)(bias + sel * DH))[lane];
    float4 o = make_float4(b.x + nscale * acc.x, b.y + nscale * acc.y,
                           b.z + nscale * acc.z, b.w + nscale * acc.w);
    ((float4*)y)[(size_t)n * 64 + ycol0 + lane] = o;
}

// ---------------------------------------------------------------- launch
extern "C" void kernel_launch(void* const* d_in, const int* in_sizes, int n_in,
                              void* d_out, int out_size)
{
    const float* x    = (const float*)d_in[0];
    const void*  ei   = d_in[1];
    const float* Wf   = (const float*)d_in[2];
    const float* Wb   = (const float*)d_in[3];
    const float* bias = (const float*)d_in[4];
    float*       y    = (float*)d_out;

    int M  = in_sizes[0] / DIN;
    int E2 = in_sizes[1];
    int E  = E2 / 2;
    int nb = (M + SB - 1) / SB;

    static cudaStream_t s1 = nullptr, s2 = nullptr;
    static cudaEvent_t ev_fork = nullptr, ev_isr = nullptr, ev_gemm = nullptr,
                       ev_fc = nullptr, ev_fr = nullptr, ev_b = nullptr;
    static bool tried = false;
    if (!tried) {
        tried = true;
        cudaFuncSetAttribute(gemm_hmma_kernel,
                             cudaFuncAttributeMaxDynamicSharedMemorySize, GEMM_SMEM);
        bool ok = (cudaStreamCreateWithFlags(&s1, cudaStreamNonBlocking) == cudaSuccess)
               && (cudaStreamCreateWithFlags(&s2, cudaStreamNonBlocking) == cudaSuccess);
        if (ok) {
            cudaEventCreateWithFlags(&ev_fork, cudaEventDisableTiming);
            cudaEventCreateWithFlags(&ev_isr, cudaEventDisableTiming);
            cudaEventCreateWithFlags(&ev_gemm, cudaEventDisableTiming);
            cudaEventCreateWithFlags(&ev_fc, cudaEventDisableTiming);
            cudaEventCreateWithFlags(&ev_fr, cudaEventDisableTiming);
            cudaEventCreateWithFlags(&ev_b, cudaEventDisableTiming);
        } else { s1 = s2 = nullptr; }
    }

    int eblocks = (E + 255) / 256;
    int gblocks = (M * 32 + 255) / 256;

    if (s1) {
        cudaEventRecord(ev_fork, 0);
        cudaStreamWaitEvent(s1, ev_fork, 0);
        cudaStreamWaitEvent(s2, ev_fork, 0);

        // s1: shared preproc head (count + isr), then c-side chain
        zero_cnt_kernel<<<(M + 255) / 256, 256, 0, s1>>>(M);
        detect_flag_kernel<<<1, 1024, 0, s1>>>((const unsigned*)ei, E2);
        count_deg_kernel<<<eblocks, 256, 0, s1>>>(ei, E);
        isr_kernel<<<(M + 255) / 256, 256, 0, s1>>>(M);
        cudaEventRecord(ev_isr, s1);

        scan_block_sums<<<nb, SB, 0, s1>>>(0, M);
        scan_bsum<<<1, SB, 0, s1>>>(0, nb);
        scan_final<<<nb, SB, 0, s1>>>(0, M);
        fill_c_kernel<<<eblocks, 256, 0, s1>>>(ei, E);
        cudaEventRecord(ev_fc, s1);

        // s2: r-side chain (waits for counts via ev_isr)
        cudaStreamWaitEvent(s2, ev_isr, 0);
        scan_block_sums<<<nb, SB, 0, s2>>>(1, M);
        scan_bsum<<<1, SB, 0, s2>>>(1, nb);
        scan_final<<<nb, SB, 0, s2>>>(1, M);
        fill_r_kernel<<<eblocks, 256, 0, s2>>>(ei, E);
        cudaEventRecord(ev_fr, s2);

        // main: GEMM path (epilogue needs isr)
        w_conv_kernel<<<256, 256>>>(Wf, Wb);
        x_conv_kernel<<<(M * 64 + 255) / 256, 256>>>(x, M);
        cudaStreamWaitEvent(0, ev_isr, 0);
        gemm_hmma_kernel<<<(M + 63) / 64, 256, GEMM_SMEM>>>(M);
        cudaEventRecord(ev_gemm, 0);

        // gathers: each starts when its fill + gemm are done
        cudaStreamWaitEvent(0, ev_fc, 0);
        gather_kernel<<<gblocks, 256, 0, 0>>>(0, bias, y, M);
        cudaStreamWaitEvent(s2, ev_gemm, 0);
        gather_kernel<<<gblocks, 256, 0, s2>>>(1, bias, y, M);
        cudaEventRecord(ev_b, s2);
        cudaStreamWaitEvent(0, ev_b, 0);
    } else {
        // serial fallback
        zero_cnt_kernel<<<(M + 255) / 256, 256>>>(M);
        detect_flag_kernel<<<1, 1024>>>((const unsigned*)ei, E2);
        count_deg_kernel<<<eblocks, 256>>>(ei, E);
        isr_kernel<<<(M + 255) / 256, 256>>>(M);
        scan_block_sums<<<nb, SB>>>(0, M);
        scan_bsum<<<1, SB>>>(0, nb);
        scan_final<<<nb, SB>>>(0, M);
        fill_c_kernel<<<eblocks, 256>>>(ei, E);
        scan_block_sums<<<nb, SB>>>(1, M);
        scan_bsum<<<1, SB>>>(1, nb);
        scan_final<<<nb, SB>>>(1, M);
        fill_r_kernel<<<eblocks, 256>>>(ei, E);
        w_conv_kernel<<<256, 256>>>(Wf, Wb);
        x_conv_kernel<<<(M * 64 + 255) / 256, 256>>>(x, M);
        gemm_hmma_kernel<<<(M + 63) / 64, 256, GEMM_SMEM>>>(M);
        gather_kernel<<<gblocks, 256>>>(0, bias, y, M);
        gather_kernel<<<gblocks, 256>>>(1, bias, y, M);
    }
}